// round 1
// baseline (speedup 1.0000x reference)
#include <cuda_runtime.h>
#include <math.h>

#define T_TOKENS 8192
#define D_DIM    1024
#define E_EXP    8
#define H_DIM    512
#define TOPK     2
#define S_SLOTS  (T_TOKENS * TOPK)      // 16384
#define MAXMT    (T_TOKENS / 128)       // 64 m-tiles per expert (worst case)

// ---------------- static device scratch (no runtime allocation) ----------------
__device__ int   g_counts[E_EXP];
__device__ int   g_offsets[E_EXP];
__device__ int   g_slot_expert[S_SLOTS];
__device__ int   g_slot_pos[S_SLOTS];
__device__ float g_slot_gate[S_SLOTS];
__device__ int   g_perm_token[S_SLOTS];   // gemm row -> token index
__device__ float g_row_gate[S_SLOTS];     // gemm row -> gate weight
__device__ int   g_row_dest[S_SLOTS];     // gemm row -> slot id (2t+k)
__device__ float g_H[(size_t)S_SLOTS * H_DIM];            // 32 MB
__device__ float g_partial[(size_t)S_SLOTS * D_DIM];      // 64 MB

// ---------------- kernel 0: zero counters ----------------
__global__ void zero_counts_kernel() {
    if (threadIdx.x < E_EXP) g_counts[threadIdx.x] = 0;
}

// ---------------- kernel 1: gating (logits, top-2, softmax) ----------------
// one warp per token, 8 warps per block; gate_w staged in smem
__global__ void gate_kernel(const float* __restrict__ x,
                            const float* __restrict__ gate_w,
                            const float* __restrict__ gate_b) {
    __shared__ float sgw[D_DIM * E_EXP];  // 32 KB
    for (int i = threadIdx.x; i < D_DIM * E_EXP / 4; i += blockDim.x)
        ((float4*)sgw)[i] = ((const float4*)gate_w)[i];
    __syncthreads();

    int warp = threadIdx.x >> 5;
    int lane = threadIdx.x & 31;
    int t = blockIdx.x * 8 + warp;
    if (t >= T_TOKENS) return;

    const float* xr = x + (size_t)t * D_DIM;
    float acc[E_EXP];
#pragma unroll
    for (int e = 0; e < E_EXP; e++) acc[e] = 0.f;

    for (int d = lane; d < D_DIM; d += 32) {
        float xv = xr[d];
        float4 a = *(const float4*)&sgw[d * E_EXP];
        float4 b = *(const float4*)&sgw[d * E_EXP + 4];
        acc[0] += xv * a.x; acc[1] += xv * a.y; acc[2] += xv * a.z; acc[3] += xv * a.w;
        acc[4] += xv * b.x; acc[5] += xv * b.y; acc[6] += xv * b.z; acc[7] += xv * b.w;
    }
#pragma unroll
    for (int o = 16; o > 0; o >>= 1)
#pragma unroll
        for (int e = 0; e < E_EXP; e++)
            acc[e] += __shfl_down_sync(0xffffffffu, acc[e], o);

    if (lane == 0) {
        float v[E_EXP];
#pragma unroll
        for (int e = 0; e < E_EXP; e++) v[e] = acc[e] + gate_b[e];
        int i0 = 0;
#pragma unroll
        for (int e = 1; e < E_EXP; e++) if (v[e] > v[i0]) i0 = e;
        int i1 = -1;
#pragma unroll
        for (int e = 0; e < E_EXP; e++)
            if (e != i0 && (i1 < 0 || v[e] > v[i1])) i1 = e;

        // softmax over the two top values (v[i0] >= v[i1])
        float e1 = expf(v[i1] - v[i0]);
        float inv = 1.f / (1.f + e1);
        float g0 = inv;
        float g1 = e1 * inv;

        int p0 = atomicAdd(&g_counts[i0], 1);
        int p1 = atomicAdd(&g_counts[i1], 1);
        int s0 = 2 * t, s1 = 2 * t + 1;
        g_slot_expert[s0] = i0; g_slot_pos[s0] = p0; g_slot_gate[s0] = g0;
        g_slot_expert[s1] = i1; g_slot_pos[s1] = p1; g_slot_gate[s1] = g1;
    }
}

// ---------------- kernel 2: exclusive scan of counts ----------------
__global__ void scan_kernel() {
    if (threadIdx.x == 0) {
        int s = 0;
#pragma unroll
        for (int e = 0; e < E_EXP; e++) { g_offsets[e] = s; s += g_counts[e]; }
    }
}

// ---------------- kernel 3: fill per-row metadata ----------------
__global__ void fill_kernel() {
    int s = blockIdx.x * blockDim.x + threadIdx.x;
    if (s >= S_SLOTS) return;
    int e = g_slot_expert[s];
    int row = g_offsets[e] + g_slot_pos[s];
    g_perm_token[row] = s >> 1;
    g_row_gate[row]   = g_slot_gate[s];
    g_row_dest[row]   = s;
}

// ---------------- SGEMM config ----------------
#define BM 128
#define BN 128
#define BK 16
#define PAD 4

__device__ __forceinline__ float gelu_exact(float v) {
    return 0.5f * v * (1.0f + erff(v * 0.70710678118654752f));
}

// GEMM1: H[row, :] = gelu( X[perm[row], :] @ W1[e] + b1[e] ),  K=1024, N=512
__global__ void __launch_bounds__(256, 2)
gemm1_kernel(const float* __restrict__ x,
             const float* __restrict__ w1,
             const float* __restrict__ b1) {
    const int e  = blockIdx.x / MAXMT;
    const int mt = blockIdx.x % MAXMT;
    const int cnt = g_counts[e];
    const int m0 = mt * BM;
    if (m0 >= cnt) return;
    const int rowbase = g_offsets[e] + m0;
    const int n0 = blockIdx.y * BN;
    const float* __restrict__ B = w1 + (size_t)e * D_DIM * H_DIM;
    const float* __restrict__ bias = b1 + (size_t)e * H_DIM;

    __shared__ float As[BK][BM + PAD];
    __shared__ float Bs[BK][BN];

    const int tid = threadIdx.x;
    const int tx = tid & 15, ty = tid >> 4;

    // A load mapping: 2 rows per thread (ar, ar+64), 4 consecutive k each
    const int ar = tid >> 2;
    const int ac = (tid & 3) * 4;
    const int r0 = m0 + ar, r1 = r0 + 64;
    const float* xp0 = (r0 < cnt) ? x + (size_t)g_perm_token[rowbase + ar]      * D_DIM : nullptr;
    const float* xp1 = (r1 < cnt) ? x + (size_t)g_perm_token[rowbase + ar + 64] * D_DIM : nullptr;

    // B load mapping: rows br, br+8, 4 consecutive n each
    const int br = tid >> 5;
    const int bc = (tid & 31) * 4;

    float acc[8][8];
#pragma unroll
    for (int i = 0; i < 8; i++)
#pragma unroll
        for (int j = 0; j < 8; j++) acc[i][j] = 0.f;

    for (int k0 = 0; k0 < D_DIM; k0 += BK) {
        float4 a0 = xp0 ? *(const float4*)(xp0 + k0 + ac) : make_float4(0.f,0.f,0.f,0.f);
        float4 a1 = xp1 ? *(const float4*)(xp1 + k0 + ac) : make_float4(0.f,0.f,0.f,0.f);
        float4 bv0 = *(const float4*)(B + (size_t)(k0 + br)     * H_DIM + n0 + bc);
        float4 bv1 = *(const float4*)(B + (size_t)(k0 + br + 8) * H_DIM + n0 + bc);
        __syncthreads();
        As[ac + 0][ar] = a0.x; As[ac + 1][ar] = a0.y; As[ac + 2][ar] = a0.z; As[ac + 3][ar] = a0.w;
        As[ac + 0][ar + 64] = a1.x; As[ac + 1][ar + 64] = a1.y; As[ac + 2][ar + 64] = a1.z; As[ac + 3][ar + 64] = a1.w;
        *(float4*)&Bs[br][bc]     = bv0;
        *(float4*)&Bs[br + 8][bc] = bv1;
        __syncthreads();
#pragma unroll
        for (int kk = 0; kk < BK; kk++) {
            float a[8], b[8];
            *(float4*)&a[0] = *(float4*)&As[kk][ty * 8];
            *(float4*)&a[4] = *(float4*)&As[kk][ty * 8 + 4];
            *(float4*)&b[0] = *(float4*)&Bs[kk][tx * 8];
            *(float4*)&b[4] = *(float4*)&Bs[kk][tx * 8 + 4];
#pragma unroll
            for (int i = 0; i < 8; i++)
#pragma unroll
                for (int j = 0; j < 8; j++) acc[i][j] += a[i] * b[j];
        }
    }

#pragma unroll
    for (int i = 0; i < 8; i++) {
        int m = ty * 8 + i;
        if (m0 + m >= cnt) continue;
        float* hp = g_H + (size_t)(rowbase + m) * H_DIM + n0 + tx * 8;
#pragma unroll
        for (int j = 0; j < 8; j++) {
            float v = acc[i][j] + bias[n0 + tx * 8 + j];
            hp[j] = gelu_exact(v);
        }
    }
}

// GEMM2: partial[dest[row], :] = gate[row] * ( H[row, :] @ W2[e] + b2[e] ),  K=512, N=1024
__global__ void __launch_bounds__(256, 2)
gemm2_kernel(const float* __restrict__ w2,
             const float* __restrict__ b2) {
    const int e  = blockIdx.x / MAXMT;
    const int mt = blockIdx.x % MAXMT;
    const int cnt = g_counts[e];
    const int m0 = mt * BM;
    if (m0 >= cnt) return;
    const int rowbase = g_offsets[e] + m0;
    const int n0 = blockIdx.y * BN;
    const float* __restrict__ B = w2 + (size_t)e * H_DIM * D_DIM;
    const float* __restrict__ bias = b2 + (size_t)e * D_DIM;

    __shared__ float As[BK][BM + PAD];
    __shared__ float Bs[BK][BN];

    const int tid = threadIdx.x;
    const int tx = tid & 15, ty = tid >> 4;

    const int ar = tid >> 2;
    const int ac = (tid & 3) * 4;
    const int r0 = m0 + ar, r1 = r0 + 64;
    const float* hp0 = (r0 < cnt) ? g_H + (size_t)(rowbase + ar)      * H_DIM : nullptr;
    const float* hp1 = (r1 < cnt) ? g_H + (size_t)(rowbase + ar + 64) * H_DIM : nullptr;

    const int br = tid >> 5;
    const int bc = (tid & 31) * 4;

    float acc[8][8];
#pragma unroll
    for (int i = 0; i < 8; i++)
#pragma unroll
        for (int j = 0; j < 8; j++) acc[i][j] = 0.f;

    for (int k0 = 0; k0 < H_DIM; k0 += BK) {
        float4 a0 = hp0 ? *(const float4*)(hp0 + k0 + ac) : make_float4(0.f,0.f,0.f,0.f);
        float4 a1 = hp1 ? *(const float4*)(hp1 + k0 + ac) : make_float4(0.f,0.f,0.f,0.f);
        float4 bv0 = *(const float4*)(B + (size_t)(k0 + br)     * D_DIM + n0 + bc);
        float4 bv1 = *(const float4*)(B + (size_t)(k0 + br + 8) * D_DIM + n0 + bc);
        __syncthreads();
        As[ac + 0][ar] = a0.x; As[ac + 1][ar] = a0.y; As[ac + 2][ar] = a0.z; As[ac + 3][ar] = a0.w;
        As[ac + 0][ar + 64] = a1.x; As[ac + 1][ar + 64] = a1.y; As[ac + 2][ar + 64] = a1.z; As[ac + 3][ar + 64] = a1.w;
        *(float4*)&Bs[br][bc]     = bv0;
        *(float4*)&Bs[br + 8][bc] = bv1;
        __syncthreads();
#pragma unroll
        for (int kk = 0; kk < BK; kk++) {
            float a[8], b[8];
            *(float4*)&a[0] = *(float4*)&As[kk][ty * 8];
            *(float4*)&a[4] = *(float4*)&As[kk][ty * 8 + 4];
            *(float4*)&b[0] = *(float4*)&Bs[kk][tx * 8];
            *(float4*)&b[4] = *(float4*)&Bs[kk][tx * 8 + 4];
#pragma unroll
            for (int i = 0; i < 8; i++)
#pragma unroll
                for (int j = 0; j < 8; j++) acc[i][j] += a[i] * b[j];
        }
    }

#pragma unroll
    for (int i = 0; i < 8; i++) {
        int m = ty * 8 + i;
        if (m0 + m >= cnt) continue;
        int row = rowbase + m;
        float gate = g_row_gate[row];
        int dest = g_row_dest[row];
        float* pp = g_partial + (size_t)dest * D_DIM + n0 + tx * 8;
#pragma unroll
        for (int j = 0; j < 8; j++) {
            float v = acc[i][j] + bias[n0 + tx * 8 + j];
            pp[j] = gate * v;
        }
    }
}

// ---------------- kernel 6: combine the two expert contributions ----------------
__global__ void combine_kernel(float* __restrict__ out) {
    size_t i = (size_t)blockIdx.x * blockDim.x + threadIdx.x;      // float4 index
    size_t total = (size_t)T_TOKENS * D_DIM / 4;
    if (i >= total) return;
    size_t t = i / (D_DIM / 4);
    size_t c = i % (D_DIM / 4);
    const float4* p0 = (const float4*)(g_partial + (size_t)(2 * t)     * D_DIM) + c;
    const float4* p1 = (const float4*)(g_partial + (size_t)(2 * t + 1) * D_DIM) + c;
    float4 a = *p0, b = *p1;
    float4 r = make_float4(a.x + b.x, a.y + b.y, a.z + b.z, a.w + b.w);
    ((float4*)out)[i] = r;
}

// ---------------- launcher ----------------
extern "C" void kernel_launch(void* const* d_in, const int* in_sizes, int n_in,
                              void* d_out, int out_size) {
    const float* x      = (const float*)d_in[0];
    const float* gate_w = (const float*)d_in[1];
    const float* gate_b = (const float*)d_in[2];
    const float* w1     = (const float*)d_in[3];
    const float* b1     = (const float*)d_in[4];
    const float* w2     = (const float*)d_in[5];
    const float* b2     = (const float*)d_in[6];
    float* out = (float*)d_out;

    zero_counts_kernel<<<1, 32>>>();
    gate_kernel<<<T_TOKENS / 8, 256>>>(x, gate_w, gate_b);
    scan_kernel<<<1, 32>>>();
    fill_kernel<<<S_SLOTS / 256, 256>>>();
    gemm1_kernel<<<dim3(E_EXP * MAXMT, H_DIM / BN), 256>>>(x, w1, b1);
    gemm2_kernel<<<dim3(E_EXP * MAXMT, D_DIM / BN), 256>>>(w2, b2);
    combine_kernel<<<(T_TOKENS * D_DIM / 4 + 255) / 256, 256>>>(out);
}

// round 4
// speedup vs baseline: 4.0241x; 4.0241x over previous
#include <cuda_runtime.h>
#include <cuda_fp16.h>
#include <math.h>
#include <stdint.h>

#define T_TOKENS 8192
#define D_DIM    1024
#define E_EXP    8
#define H_DIM    512
#define S_SLOTS  (T_TOKENS * 2)
#define MAXMT    64

// ---------------- static device scratch ----------------
__device__ int    g_counts[E_EXP];
__device__ int    g_offsets[E_EXP];
__device__ int    g_slot_expert[S_SLOTS];
__device__ int    g_slot_pos[S_SLOTS];
__device__ float  g_slot_gate[S_SLOTS];
__device__ int    g_perm_token[S_SLOTS];
__device__ float  g_row_gate[S_SLOTS];
__device__ int    g_row_dest[S_SLOTS];
__device__ __half g_xh[(size_t)T_TOKENS * D_DIM];          // 16 MB
__device__ __half g_Hh[(size_t)S_SLOTS * H_DIM];           // 16 MB
__device__ __half g_w1h[(size_t)E_EXP * D_DIM * H_DIM];    // 8 MB
__device__ __half g_w2h[(size_t)E_EXP * H_DIM * D_DIM];    // 8 MB
__device__ float  g_partial[(size_t)S_SLOTS * D_DIM];      // 64 MB

// ---------------- PTX helpers ----------------
__device__ __forceinline__ uint32_t smem_u32(const void* p) {
    uint32_t a;
    asm("{ .reg .u64 t; cvta.to.shared.u64 t, %1; cvt.u32.u64 %0, t; }" : "=r"(a) : "l"(p));
    return a;
}
#define CP_ASYNC16(dst, src) \
    asm volatile("cp.async.cg.shared.global [%0], [%1], 16;" :: "r"(dst), "l"(src))
#define CP_COMMIT() asm volatile("cp.async.commit_group;" ::: "memory")
#define CP_WAIT2()  asm volatile("cp.async.wait_group 2;" ::: "memory")

#define LDMATRIX_X4(r0,r1,r2,r3,addr) \
    asm volatile("ldmatrix.sync.aligned.m8n8.x4.shared.b16 {%0,%1,%2,%3}, [%4];" \
        : "=r"(r0), "=r"(r1), "=r"(r2), "=r"(r3) : "r"(addr))
#define LDMATRIX_X4_T(r0,r1,r2,r3,addr) \
    asm volatile("ldmatrix.sync.aligned.m8n8.x4.trans.shared.b16 {%0,%1,%2,%3}, [%4];" \
        : "=r"(r0), "=r"(r1), "=r"(r2), "=r"(r3) : "r"(addr))
#define MMA_16816(c0,c1,c2,c3,a0,a1,a2,a3,b0,b1) \
    asm volatile("mma.sync.aligned.m16n8k16.row.col.f32.f16.f16.f32 " \
        "{%0,%1,%2,%3}, {%4,%5,%6,%7}, {%8,%9}, {%0,%1,%2,%3};" \
        : "+f"(c0), "+f"(c1), "+f"(c2), "+f"(c3) \
        : "r"(a0), "r"(a1), "r"(a2), "r"(a3), "r"(b0), "r"(b1))

// ---------------- kernel 0: zero counters ----------------
__global__ void zero_counts_kernel() {
    if (threadIdx.x < E_EXP) g_counts[threadIdx.x] = 0;
}

// ---------------- kernel 1: gating (fp32) ----------------
__global__ void gate_kernel(const float* __restrict__ x,
                            const float* __restrict__ gate_w,
                            const float* __restrict__ gate_b) {
    __shared__ float sgw[D_DIM * E_EXP];
    for (int i = threadIdx.x; i < D_DIM * E_EXP / 4; i += blockDim.x)
        ((float4*)sgw)[i] = ((const float4*)gate_w)[i];
    __syncthreads();

    int warp = threadIdx.x >> 5;
    int lane = threadIdx.x & 31;
    int t = blockIdx.x * 8 + warp;
    if (t >= T_TOKENS) return;

    const float* xr = x + (size_t)t * D_DIM;
    float acc[E_EXP];
#pragma unroll
    for (int e = 0; e < E_EXP; e++) acc[e] = 0.f;
    for (int d = lane; d < D_DIM; d += 32) {
        float xv = xr[d];
        float4 a = *(const float4*)&sgw[d * E_EXP];
        float4 b = *(const float4*)&sgw[d * E_EXP + 4];
        acc[0] += xv * a.x; acc[1] += xv * a.y; acc[2] += xv * a.z; acc[3] += xv * a.w;
        acc[4] += xv * b.x; acc[5] += xv * b.y; acc[6] += xv * b.z; acc[7] += xv * b.w;
    }
#pragma unroll
    for (int o = 16; o > 0; o >>= 1)
#pragma unroll
        for (int e = 0; e < E_EXP; e++)
            acc[e] += __shfl_down_sync(0xffffffffu, acc[e], o);

    if (lane == 0) {
        float v[E_EXP];
#pragma unroll
        for (int e = 0; e < E_EXP; e++) v[e] = acc[e] + gate_b[e];
        int i0 = 0;
#pragma unroll
        for (int e = 1; e < E_EXP; e++) if (v[e] > v[i0]) i0 = e;
        int i1 = -1;
#pragma unroll
        for (int e = 0; e < E_EXP; e++)
            if (e != i0 && (i1 < 0 || v[e] > v[i1])) i1 = e;
        float e1 = expf(v[i1] - v[i0]);
        float inv = 1.f / (1.f + e1);
        int p0 = atomicAdd(&g_counts[i0], 1);
        int p1 = atomicAdd(&g_counts[i1], 1);
        int s0 = 2 * t, s1 = 2 * t + 1;
        g_slot_expert[s0] = i0; g_slot_pos[s0] = p0; g_slot_gate[s0] = inv;
        g_slot_expert[s1] = i1; g_slot_pos[s1] = p1; g_slot_gate[s1] = e1 * inv;
    }
}

// ---------------- kernel 2/3: scan + fill ----------------
__global__ void scan_kernel() {
    if (threadIdx.x == 0) {
        int s = 0;
#pragma unroll
        for (int e = 0; e < E_EXP; e++) { g_offsets[e] = s; s += g_counts[e]; }
    }
}
__global__ void fill_kernel() {
    int s = blockIdx.x * blockDim.x + threadIdx.x;
    if (s >= S_SLOTS) return;
    int e = g_slot_expert[s];
    int row = g_offsets[e] + g_slot_pos[s];
    g_perm_token[row] = s >> 1;
    g_row_gate[row]   = g_slot_gate[s];
    g_row_dest[row]   = s;
}

// ---------------- fp32 -> fp16 converts (device-global destinations) ----------------
template<int WHICH>   // 0: x -> g_xh, 1: w1 -> g_w1h, 2: w2 -> g_w2h
__global__ void f2h_kernel(const float* __restrict__ in, int n4) {
    int i = blockIdx.x * blockDim.x + threadIdx.x;
    if (i >= n4) return;
    __half* out = (WHICH == 0) ? g_xh : (WHICH == 1) ? g_w1h : g_w2h;
    float4 v = ((const float4*)in)[i];
    __half2* o = (__half2*)out + 2 * (size_t)i;
    o[0] = __floats2half2_rn(v.x, v.y);
    o[1] = __floats2half2_rn(v.z, v.w);
}

// ---------------- fp16 tensor-core grouped GEMM ----------------
// Tile 128(M) x 128(N) x 32(K), 4-stage cp.async pipeline, 8 warps (2M x 4N).
#define SA 40            // A smem row stride in halves (80B -> conflict-free ldmatrix)
#define SB 136           // B smem row stride in halves (272B -> conflict-free ldmatrix)
#define A_STAGE (128 * SA * 2)   // 10240 B
#define B_STAGE (32 * SB * 2)    // 8704 B
#define OFF_A   1024
#define OFF_B   (OFF_A + 4 * A_STAGE)
#define GEMM_SMEM (OFF_B + 4 * B_STAGE)   // 76800 B

__device__ __forceinline__ float gelu_exact(float v) {
    return 0.5f * v * (1.0f + erff(v * 0.70710678118654752f));
}

template<int K_TOTAL, bool FIRST>
__global__ void __launch_bounds__(256, 2)
moe_gemm_hmma(const float* __restrict__ bias)  // [E][N_TOT]
{
    constexpr int N_TOT = FIRST ? H_DIM : D_DIM;
    constexpr int NIT   = K_TOTAL / 32;

    const __half* __restrict__ Ag = FIRST ? g_xh  : g_Hh;
    const __half* __restrict__ Wh = FIRST ? g_w1h : g_w2h;

    const int e  = blockIdx.x / MAXMT;
    const int mt = blockIdx.x % MAXMT;
    const int cnt = g_counts[e];
    const int m0 = mt * 128;
    if (m0 >= cnt) return;
    const int rowbase = g_offsets[e] + m0;
    const int n0 = blockIdx.y * 128;

    extern __shared__ __align__(128) char gsm[];
    float* sbias = (float*)gsm;          // 128 floats
    uint32_t sb = smem_u32(gsm);

    const int tid  = threadIdx.x;
    const int wid  = tid >> 5;
    const int lane = tid & 31;

    if (tid < 128) sbias[tid] = bias[(size_t)e * N_TOT + n0 + tid];

    // ---- per-thread load mapping ----
    int arow_l = tid >> 1;
    int arow_g = rowbase + arow_l;
    if (arow_g > S_SLOTS - 1) arow_g = S_SLOTS - 1;
    const __half* aptr;
    if (FIRST) aptr = Ag + (size_t)g_perm_token[arow_g] * D_DIM + (tid & 1) * 16;
    else       aptr = Ag + (size_t)arow_g * H_DIM + (tid & 1) * 16;
    const uint32_t a_dst0 = sb + OFF_A + (uint32_t)arow_l * (SA * 2) + (uint32_t)(tid & 1) * 32;

    const int brow = tid >> 3;
    const __half* bptr = Wh + ((size_t)e * K_TOTAL + brow) * N_TOT + n0 + (tid & 7) * 16;
    const uint32_t b_dst0 = sb + OFF_B + (uint32_t)brow * (SB * 2) + (uint32_t)(tid & 7) * 32;

#define LOAD_STAGE(pf) do { \
        uint32_t ad = a_dst0 + ((pf) & 3) * A_STAGE; \
        const __half* as_ = aptr + (pf) * 32; \
        CP_ASYNC16(ad, as_); CP_ASYNC16(ad + 16, as_ + 8); \
        uint32_t bd = b_dst0 + ((pf) & 3) * B_STAGE; \
        const __half* bs_ = bptr + (size_t)(pf) * 32 * N_TOT; \
        CP_ASYNC16(bd, bs_); CP_ASYNC16(bd + 16, bs_ + 8); \
    } while (0)

    LOAD_STAGE(0); CP_COMMIT();
    LOAD_STAGE(1); CP_COMMIT();
    LOAD_STAGE(2); CP_COMMIT();

    // ---- warp tiling: 2 (M) x 4 (N); warp tile 64x32 ----
    const int m0w = (wid & 1) * 64;
    const int n0w = (wid >> 1) * 32;

    float c[4][4][4];
#pragma unroll
    for (int mi = 0; mi < 4; mi++)
#pragma unroll
        for (int ni = 0; ni < 4; ni++)
#pragma unroll
            for (int q = 0; q < 4; q++) c[mi][ni][q] = 0.f;

    const uint32_t a_lm = sb + OFF_A
        + (uint32_t)(m0w + (lane & 15)) * (SA * 2) + (uint32_t)(lane >> 4) * 16;
    const uint32_t b_lm = sb + OFF_B
        + (uint32_t)(lane & 15) * (SB * 2)
        + (uint32_t)n0w * 2 + (uint32_t)(lane >> 4) * 16;

    for (int i = 0; i < NIT; ++i) {
        CP_WAIT2();
        __syncthreads();
        if (i + 3 < NIT) LOAD_STAGE(i + 3);
        CP_COMMIT();                       // ALWAYS commit: keeps wait_group accounting valid

        const uint32_t abuf = a_lm + (i & 3) * A_STAGE;
        const uint32_t bbuf = b_lm + (i & 3) * B_STAGE;
#pragma unroll
        for (int ks = 0; ks < 2; ++ks) {
            uint32_t af[4][4], bf[2][4];
#pragma unroll
            for (int mi = 0; mi < 4; mi++)
                LDMATRIX_X4(af[mi][0], af[mi][1], af[mi][2], af[mi][3],
                            abuf + (uint32_t)(mi * 16) * (SA * 2) + ks * 32);
#pragma unroll
            for (int nj = 0; nj < 2; nj++)
                LDMATRIX_X4_T(bf[nj][0], bf[nj][1], bf[nj][2], bf[nj][3],
                              bbuf + (uint32_t)(ks * 16) * (SB * 2) + nj * 32);
#pragma unroll
            for (int mi = 0; mi < 4; mi++)
#pragma unroll
                for (int ni = 0; ni < 4; ni++) {
                    int nj = ni >> 1, h = ni & 1;
                    MMA_16816(c[mi][ni][0], c[mi][ni][1], c[mi][ni][2], c[mi][ni][3],
                              af[mi][0], af[mi][1], af[mi][2], af[mi][3],
                              bf[nj][h * 2], bf[nj][h * 2 + 1]);
                }
        }
        __syncthreads();
    }

    // ---- epilogue ----
    const int g   = lane >> 2;
    const int tig = lane & 3;
#pragma unroll
    for (int mi = 0; mi < 4; mi++) {
#pragma unroll
        for (int half = 0; half < 2; half++) {
            int rl = m0w + mi * 16 + g + half * 8;
            if (m0 + rl >= cnt) continue;
            int grow = rowbase + rl;
            if (FIRST) {
                __half* dst = g_Hh + (size_t)grow * H_DIM + n0;
#pragma unroll
                for (int ni = 0; ni < 4; ni++) {
                    int col = n0w + ni * 8 + tig * 2;
                    float v0 = c[mi][ni][half * 2 + 0] + sbias[col];
                    float v1 = c[mi][ni][half * 2 + 1] + sbias[col + 1];
                    *(__half2*)(dst + col) = __floats2half2_rn(gelu_exact(v0), gelu_exact(v1));
                }
            } else {
                float gate = g_row_gate[grow];
                int dest = g_row_dest[grow];
                float* dst = g_partial + (size_t)dest * D_DIM + n0;
#pragma unroll
                for (int ni = 0; ni < 4; ni++) {
                    int col = n0w + ni * 8 + tig * 2;
                    float v0 = gate * (c[mi][ni][half * 2 + 0] + sbias[col]);
                    float v1 = gate * (c[mi][ni][half * 2 + 1] + sbias[col + 1]);
                    *(float2*)(dst + col) = make_float2(v0, v1);
                }
            }
        }
    }
}

// ---------------- combine ----------------
__global__ void combine_kernel(float* __restrict__ out) {
    size_t i = (size_t)blockIdx.x * blockDim.x + threadIdx.x;
    size_t total = (size_t)T_TOKENS * D_DIM / 4;
    if (i >= total) return;
    size_t t = i / (D_DIM / 4);
    size_t c = i % (D_DIM / 4);
    const float4* p0 = (const float4*)(g_partial + (size_t)(2 * t)     * D_DIM) + c;
    const float4* p1 = (const float4*)(g_partial + (size_t)(2 * t + 1) * D_DIM) + c;
    float4 a = *p0, b = *p1;
    ((float4*)out)[i] = make_float4(a.x + b.x, a.y + b.y, a.z + b.z, a.w + b.w);
}

// ---------------- launcher ----------------
extern "C" void kernel_launch(void* const* d_in, const int* in_sizes, int n_in,
                              void* d_out, int out_size) {
    const float* x      = (const float*)d_in[0];
    const float* gate_w = (const float*)d_in[1];
    const float* gate_b = (const float*)d_in[2];
    const float* w1     = (const float*)d_in[3];
    const float* b1     = (const float*)d_in[4];
    const float* w2     = (const float*)d_in[5];
    const float* b2     = (const float*)d_in[6];
    float* out = (float*)d_out;

    cudaFuncSetAttribute(moe_gemm_hmma<1024, true>,
                         cudaFuncAttributeMaxDynamicSharedMemorySize, GEMM_SMEM);
    cudaFuncSetAttribute(moe_gemm_hmma<512, false>,
                         cudaFuncAttributeMaxDynamicSharedMemorySize, GEMM_SMEM);

    zero_counts_kernel<<<1, 32>>>();
    gate_kernel<<<T_TOKENS / 8, 256>>>(x, gate_w, gate_b);
    scan_kernel<<<1, 32>>>();
    fill_kernel<<<S_SLOTS / 256, 256>>>();

    f2h_kernel<0><<<(T_TOKENS * D_DIM / 4 + 255) / 256, 256>>>(x, T_TOKENS * D_DIM / 4);
    f2h_kernel<1><<<(E_EXP * D_DIM * H_DIM / 4 + 255) / 256, 256>>>(w1, E_EXP * D_DIM * H_DIM / 4);
    f2h_kernel<2><<<(E_EXP * H_DIM * D_DIM / 4 + 255) / 256, 256>>>(w2, E_EXP * H_DIM * D_DIM / 4);

    moe_gemm_hmma<1024, true><<<dim3(E_EXP * MAXMT, H_DIM / 128), 256, GEMM_SMEM>>>(b1);
    moe_gemm_hmma<512, false><<<dim3(E_EXP * MAXMT, D_DIM / 128), 256, GEMM_SMEM>>>(b2);

    combine_kernel<<<(T_TOKENS * D_DIM / 4 + 255) / 256, 256>>>(out);
}